// round 4
// baseline (speedup 1.0000x reference)
#include <cuda_runtime.h>

#define Bb  16
#define H4  4096
#define KC  64          // k-chunk per block
#define NKC 16          // 1024 / KC
#define NSPLIT 32       // NKC * 2 matrices
#define TPB 256
#define BPH 8           // batches per thread (half of Bb)
#define PD  8           // LDG prefetch depth

// scratch: split-K partials [NSPLIT][B][4H] (8 MB) and reduced pre-activations
__device__ float g_part[(size_t)NSPLIT * Bb * H4];
__device__ float g_ifgo[(size_t)Bb * H4];

__device__ __forceinline__ unsigned long long pack2(float lo, float hi) {
    unsigned long long r;
    asm("mov.b64 %0, {%1, %2};" : "=l"(r) : "f"(lo), "f"(hi));
    return r;
}
__device__ __forceinline__ unsigned long long fma2(unsigned long long a,
                                                   unsigned long long b,
                                                   unsigned long long c) {
    unsigned long long d;
    asm("fma.rn.f32x2 %0, %1, %2, %3;" : "=l"(d) : "l"(a), "l"(b), "l"(c));
    return d;
}
__device__ __forceinline__ void unpack2(unsigned long long v, float& lo, float& hi) {
    asm("mov.b64 {%0, %1}, %2;" : "=f"(lo), "=f"(hi) : "l"(v));
}

// ---------------------------------------------------------------------------
// Kernel 1: split-K GEMM partials, software-pipelined weight stream.
// grid = (16 j-tiles, 16 k-chunks, 2 matrices) = 512 blocks, 256 threads.
// Threads 0-127: batches 0-7; threads 128-255: batches 8-15.
// Per thread: 2 output columns (LDG.64) x 8 batches = 8 f32x2 accumulators;
// PD=8 float2 prefetch buffers keep 2KB/warp of loads in flight.
// ---------------------------------------------------------------------------
__global__ __launch_bounds__(TPB) void gemm_part(
    const float* __restrict__ Wi, const float* __restrict__ Wh,
    const float* __restrict__ x,  const float* __restrict__ h)
{
    // activations duplicated {a,a}; layout [k][b], row = 16 ull = 128 B
    __shared__ unsigned long long sh[KC][Bb];

    const int jt  = blockIdx.x;   // 0..15
    const int kc  = blockIdx.y;   // 0..15
    const int mat = blockIdx.z;   // 0: Wi/x, 1: Wh/h
    const float* __restrict__ W   = mat ? Wh : Wi;
    const float* __restrict__ act = mat ? h  : x;
    const int k0   = kc * KC;
    const int tid  = threadIdx.x;
    const int lane = tid & 127;        // column-group id (2 cols each)
    const int b0   = (tid >> 7) * BPH; // 0 or 8

    // stage activation chunk (1024 values), duplicated into both f32x2 lanes
    for (int i = tid; i < Bb * KC; i += TPB) {
        int k = i >> 4;
        int b = i & 15;
        float v = act[b * 1024 + k0 + k];
        sh[k][b] = pack2(v, v);
    }

    const int j0 = jt * 256 + lane * 2;
    const float* Wp = W + (size_t)k0 * H4 + j0;

    // prologue: fill PD prefetch buffers (independent of __syncthreads)
    float2 buf[PD];
#pragma unroll
    for (int p = 0; p < PD; p++)
        buf[p] = *reinterpret_cast<const float2*>(Wp + (size_t)p * H4);

    unsigned long long acc[BPH];
#pragma unroll
    for (int b = 0; b < BPH; b++) acc[b] = 0ull;

    __syncthreads();

#pragma unroll
    for (int kk = 0; kk < KC; kk += PD) {
#pragma unroll
        for (int p = 0; p < PD; p++) {
            float2 w = buf[p];
            if (kk + PD < KC)   // compile-time predicate (fully unrolled)
                buf[p] = *reinterpret_cast<const float2*>(
                    Wp + (size_t)(kk + PD + p) * H4);
            unsigned long long wv = pack2(w.x, w.y);
            const int k = kk + p;
#pragma unroll
            for (int bi = 0; bi < BPH; bi += 2) {
                // one LDS.128 pulls two duplicated activation pairs (broadcast)
                ulonglong2 a2 = *reinterpret_cast<const ulonglong2*>(&sh[k][b0 + bi]);
                acc[bi]     = fma2(wv, a2.x, acc[bi]);
                acc[bi + 1] = fma2(wv, a2.y, acc[bi + 1]);
            }
        }
    }

    const int s = mat * NKC + kc;
    float* outp = g_part + ((size_t)s * Bb + b0) * H4 + j0;
#pragma unroll
    for (int b = 0; b < BPH; b++) {
        float f0, f1;
        unpack2(acc[b], f0, f1);
        *reinterpret_cast<float2*>(outp + (size_t)b * H4) = make_float2(f0, f1);
    }
}

// ---------------------------------------------------------------------------
// Kernel 2: reduce 32 partials + biases -> g_ifgo  (float4, MLP ~32)
// ---------------------------------------------------------------------------
__global__ __launch_bounds__(256) void reduce_bias(
    const float* __restrict__ Wib, const float* __restrict__ Whb)
{
    int idx4 = (blockIdx.x * blockDim.x + threadIdx.x) * 4;   // 0 .. B*4H
    int j = idx4 & (H4 - 1);
    float4 bi = *reinterpret_cast<const float4*>(Wib + j);
    float4 bh = *reinterpret_cast<const float4*>(Whb + j);
    float4 v = make_float4(bi.x + bh.x, bi.y + bh.y, bi.z + bh.z, bi.w + bh.w);
#pragma unroll
    for (int s = 0; s < NSPLIT; s++) {
        float4 p = *reinterpret_cast<const float4*>(g_part + (size_t)s * Bb * H4 + idx4);
        v.x += p.x; v.y += p.y; v.z += p.z; v.w += p.w;
    }
    *reinterpret_cast<float4*>(g_ifgo + idx4) = v;
}

// ---------------------------------------------------------------------------
// Kernel 3: LSTM gates + state update.  out = [h_new (B*H) | c_new (B*H)]
// ---------------------------------------------------------------------------
__global__ __launch_bounds__(256) void gates_kernel(
    const float* __restrict__ c, float* __restrict__ out)
{
    int idx = blockIdx.x * blockDim.x + threadIdx.x;   // 0 .. B*H
    int b = idx >> 10;
    int n = idx & 1023;
    const float* row = g_ifgo + (size_t)b * H4;
    float iv = row[n];
    float fv = row[1024 + n];
    float gv = row[2048 + n];
    float ov = row[3072 + n];
    float ig = 1.0f / (1.0f + expf(-iv));
    float fg = 1.0f / (1.0f + expf(-fv));
    float gg = tanhf(gv);
    float og = 1.0f / (1.0f + expf(-ov));
    float cn = fg * c[idx] + ig * gg;
    float hn = og * tanhf(cn);
    out[idx] = hn;
    out[Bb * 1024 + idx] = cn;
}

// ---------------------------------------------------------------------------
// Inputs (metadata order): x, h, c, context, Wi, Wi_b, Wh, Wh_b, AZ_il, AZ_ir,
// AZ_hl, AZ_hr.  context / AZ_* are dead (multiplied by 0 in the reference).
// ---------------------------------------------------------------------------
extern "C" void kernel_launch(void* const* d_in, const int* in_sizes, int n_in,
                              void* d_out, int out_size)
{
    (void)in_sizes; (void)n_in; (void)out_size;
    const float* x   = (const float*)d_in[0];
    const float* h   = (const float*)d_in[1];
    const float* c   = (const float*)d_in[2];
    const float* Wi  = (const float*)d_in[4];
    const float* Wib = (const float*)d_in[5];
    const float* Wh  = (const float*)d_in[6];
    const float* Whb = (const float*)d_in[7];
    float* out = (float*)d_out;

    dim3 g1(16, NKC, 2);
    gemm_part<<<g1, TPB>>>(Wi, Wh, x, h);
    reduce_bias<<<(Bb * H4) / (256 * 4), 256>>>(Wib, Whb);
    gates_kernel<<<(Bb * 1024) / 256, 256>>>(c, out);
}

// round 6
// speedup vs baseline: 1.0960x; 1.0960x over previous
#include <cuda_runtime.h>

#define Bb  16
#define H4  4096
#define KC  64          // k-chunk per block
#define NKC 16          // 1024 / KC
#define NSPLIT 32       // NKC * 2 matrices
#define TPB 128
#define BPH 8           // batches per block-half
#define PD  8           // LDG prefetch depth

// scratch: split-K partials, stored as 256 float2-planes of [H4]:
// plane index = ((s*2 + half)*4 + q), value = {acc(b=8h+2q), acc(b=8h+2q+1)}
__device__ float g_part[(size_t)NSPLIT * Bb * H4];
__device__ float g_ifgo[(size_t)Bb * H4];

__device__ __forceinline__ unsigned long long pack2(float lo, float hi) {
    unsigned long long r;
    asm("mov.b64 %0, {%1, %2};" : "=l"(r) : "f"(lo), "f"(hi));
    return r;
}
__device__ __forceinline__ unsigned long long fma2(unsigned long long a,
                                                   unsigned long long b,
                                                   unsigned long long c) {
    unsigned long long d;
    asm("fma.rn.f32x2 %0, %1, %2, %3;" : "=l"(d) : "l"(a), "l"(b), "l"(c));
    return d;
}

// ---------------------------------------------------------------------------
// Kernel 1: split-K GEMM partials.
// grid = (8 j-tiles, 16 k-chunks, 4 = {mat x batch-half}), block = 128.
// Per thread: 4 columns (LDG.128 weights) x 8 batches as 4 f32x2 batch-pairs
// -> 16 f32x2 accumulators.  Per k-step: 2 LDS.128 + 1 LDG.128 + 16 FFMA2.
// Activations stored UNduplicated; weights duplicated into f32x2 via pack2.
// ---------------------------------------------------------------------------
__global__ __launch_bounds__(TPB) void gemm_part(
    const float* __restrict__ Wi, const float* __restrict__ Wh,
    const float* __restrict__ x,  const float* __restrict__ h)
{
    __shared__ float sh_act[KC][Bb];   // 4 KB, plain floats

    const int jt   = blockIdx.x;       // 0..7
    const int kc   = blockIdx.y;       // 0..15
    const int mat  = blockIdx.z >> 1;  // 0: Wi/x, 1: Wh/h
    const int half = blockIdx.z & 1;   // batches 0-7 or 8-15
    const float* __restrict__ W   = mat ? Wh : Wi;
    const float* __restrict__ act = mat ? h  : x;
    const int k0  = kc * KC;
    const int tid = threadIdx.x;
    const int b0  = half * BPH;

    // stage activation chunk: KC x 16 floats
    for (int i = tid; i < Bb * KC; i += TPB) {
        int k = i >> 4;
        int b = i & 15;
        sh_act[k][b] = act[b * 1024 + k0 + k];
    }

    const int j0 = jt * (TPB * 4) + tid * 4;
    const float* Wp = W + (size_t)k0 * H4 + j0;

    // prologue: fill PD prefetch buffers (independent of smem)
    float4 buf[PD];
#pragma unroll
    for (int p = 0; p < PD; p++)
        buf[p] = *reinterpret_cast<const float4*>(Wp + (size_t)p * H4);

    unsigned long long acc[4][4];      // [col][batch-pair]
#pragma unroll
    for (int c = 0; c < 4; c++)
#pragma unroll
        for (int q = 0; q < 4; q++) acc[c][q] = 0ull;

    __syncthreads();

#pragma unroll
    for (int kk = 0; kk < KC; kk += PD) {
#pragma unroll
        for (int p = 0; p < PD; p++) {
            float4 w = buf[p];
            if (kk + PD < KC)   // compile-time (fully unrolled)
                buf[p] = *reinterpret_cast<const float4*>(
                    Wp + (size_t)(kk + PD + p) * H4);
            const int k = kk + p;
            // 2 LDS.128: 8 activations as 4 f32x2 batch-pairs
            ulonglong2 A0 = *reinterpret_cast<const ulonglong2*>(&sh_act[k][b0]);
            ulonglong2 A1 = *reinterpret_cast<const ulonglong2*>(&sh_act[k][b0 + 4]);
            unsigned long long wv0 = pack2(w.x, w.x);
            unsigned long long wv1 = pack2(w.y, w.y);
            unsigned long long wv2 = pack2(w.z, w.z);
            unsigned long long wv3 = pack2(w.w, w.w);
            acc[0][0] = fma2(wv0, A0.x, acc[0][0]);
            acc[0][1] = fma2(wv0, A0.y, acc[0][1]);
            acc[0][2] = fma2(wv0, A1.x, acc[0][2]);
            acc[0][3] = fma2(wv0, A1.y, acc[0][3]);
            acc[1][0] = fma2(wv1, A0.x, acc[1][0]);
            acc[1][1] = fma2(wv1, A0.y, acc[1][1]);
            acc[1][2] = fma2(wv1, A1.x, acc[1][2]);
            acc[1][3] = fma2(wv1, A1.y, acc[1][3]);
            acc[2][0] = fma2(wv2, A0.x, acc[2][0]);
            acc[2][1] = fma2(wv2, A0.y, acc[2][1]);
            acc[2][2] = fma2(wv2, A1.x, acc[2][2]);
            acc[2][3] = fma2(wv2, A1.y, acc[2][3]);
            acc[3][0] = fma2(wv3, A0.x, acc[3][0]);
            acc[3][1] = fma2(wv3, A0.y, acc[3][1]);
            acc[3][2] = fma2(wv3, A1.x, acc[3][2]);
            acc[3][3] = fma2(wv3, A1.y, acc[3][3]);
        }
    }

    // epilogue: coalesced STG.128 into per-(s,half,q) float2 planes
    const int s = mat * NKC + kc;
#pragma unroll
    for (int q = 0; q < 4; q++) {
        float2* plane = reinterpret_cast<float2*>(g_part)
                      + (size_t)((s * 2 + half) * 4 + q) * H4;
        *reinterpret_cast<ulonglong2*>(plane + j0) =
            make_ulonglong2(acc[0][q], acc[1][q]);
        *reinterpret_cast<ulonglong2*>(plane + j0 + 2) =
            make_ulonglong2(acc[2][q], acc[3][q]);
    }
}

// ---------------------------------------------------------------------------
// Kernel 2: reduce 32 partials + biases -> g_ifgo.
// 16384 threads; thread handles (half, q, j-pair) -> 4 outputs.
// ---------------------------------------------------------------------------
__global__ __launch_bounds__(256) void reduce_bias(
    const float* __restrict__ Wib, const float* __restrict__ Whb)
{
    int t  = blockIdx.x * blockDim.x + threadIdx.x;   // 0..16383
    int j  = (t & 2047) * 2;
    int hq = t >> 11;                                  // 0..7 = half*4+q
    const float4* base = reinterpret_cast<const float4*>(g_part) + (((size_t)hq * H4 + j) >> 1);
    // v = {be(j), bo(j), be(j+1), bo(j+1)}
    float4 v = make_float4(0.f, 0.f, 0.f, 0.f);
#pragma unroll
    for (int s = 0; s < NSPLIT; s++) {
        float4 p = base[(size_t)s * 4 * H4];   // advance 8 planes of H4 float2 = 4*H4 float4... 
        v.x += p.x; v.y += p.y; v.z += p.z; v.w += p.w;
    }
    float2 bb = make_float2(Wib[j] + Whb[j], Wib[j + 1] + Whb[j + 1]);
    int hh = hq >> 2, q = hq & 3;
    int be = hh * 8 + q * 2;
    *reinterpret_cast<float2*>(g_ifgo + (size_t)be * H4 + j) =
        make_float2(v.x + bb.x, v.z + bb.y);
    *reinterpret_cast<float2*>(g_ifgo + (size_t)(be + 1) * H4 + j) =
        make_float2(v.y + bb.x, v.w + bb.y);
}

// ---------------------------------------------------------------------------
// Kernel 3: LSTM gates + state update.  out = [h_new (B*H) | c_new (B*H)]
// ---------------------------------------------------------------------------
__global__ __launch_bounds__(256) void gates_kernel(
    const float* __restrict__ c, float* __restrict__ out)
{
    int idx = blockIdx.x * blockDim.x + threadIdx.x;   // 0 .. B*H
    int b = idx >> 10;
    int n = idx & 1023;
    const float* row = g_ifgo + (size_t)b * H4;
    float iv = row[n];
    float fv = row[1024 + n];
    float gv = row[2048 + n];
    float ov = row[3072 + n];
    float ig = 1.0f / (1.0f + expf(-iv));
    float fg = 1.0f / (1.0f + expf(-fv));
    float gg = tanhf(gv);
    float og = 1.0f / (1.0f + expf(-ov));
    float cn = fg * c[idx] + ig * gg;
    float hn = og * tanhf(cn);
    out[idx] = hn;
    out[Bb * 1024 + idx] = cn;
}

// ---------------------------------------------------------------------------
// Inputs (metadata order): x, h, c, context, Wi, Wi_b, Wh, Wh_b, AZ_il, AZ_ir,
// AZ_hl, AZ_hr.  context / AZ_* are dead (multiplied by 0 in the reference).
// ---------------------------------------------------------------------------
extern "C" void kernel_launch(void* const* d_in, const int* in_sizes, int n_in,
                              void* d_out, int out_size)
{
    (void)in_sizes; (void)n_in; (void)out_size;
    const float* x   = (const float*)d_in[0];
    const float* h   = (const float*)d_in[1];
    const float* c   = (const float*)d_in[2];
    const float* Wi  = (const float*)d_in[4];
    const float* Wib = (const float*)d_in[5];
    const float* Wh  = (const float*)d_in[6];
    const float* Whb = (const float*)d_in[7];
    float* out = (float*)d_out;

    dim3 g1(8, NKC, 4);
    gemm_part<<<g1, TPB>>>(Wi, Wh, x, h);
    reduce_bias<<<16384 / 256, 256>>>(Wib, Whb);
    gates_kernel<<<(Bb * 1024) / 256, 256>>>(c, out);
}

// round 7
// speedup vs baseline: 1.2003x; 1.0952x over previous
#include <cuda_runtime.h>
#include <cstdint>

#define Bb   16
#define H4   4096
#define KC   64            // k-rows per block
#define NKC  16            // k-chunks (1024 / KC)
#define NSPLIT 32          // NKC * 2 matrices
#define TPB  256
#define SK   8             // k-rows per pipeline stage
#define NST  (KC / SK)     // 8 stages
#define JT   512           // columns per j-tile (2KB rows)
#define ROW_BYTES (JT * 4)
#define STAGE_BYTES (SK * ROW_BYTES)

// scratch: 256 float2-planes of [H4]; plane p = s*8 + q holds pair {b=2q, b=2q+1}
__device__ float g_part[(size_t)NSPLIT * Bb * H4];   // 8 MB
__device__ float g_ifgo[(size_t)Bb * H4];

__device__ __forceinline__ unsigned long long pack2(float lo, float hi) {
    unsigned long long r;
    asm("mov.b64 %0, {%1, %2};" : "=l"(r) : "f"(lo), "f"(hi));
    return r;
}
__device__ __forceinline__ unsigned long long fma2(unsigned long long a,
                                                   unsigned long long b,
                                                   unsigned long long c) {
    unsigned long long d;
    asm("fma.rn.f32x2 %0, %1, %2, %3;" : "=l"(d) : "l"(a), "l"(b), "l"(c));
    return d;
}
__device__ __forceinline__ uint32_t smem_u32(const void* p) {
    uint32_t a;
    asm("{ .reg .u64 t; cvta.to.shared.u64 t, %1; cvt.u32.u64 %0, t; }"
        : "=r"(a) : "l"(p));
    return a;
}
__device__ __forceinline__ void mbar_init(uint32_t mbar, uint32_t cnt) {
    asm volatile("mbarrier.init.shared.b64 [%0], %1;" :: "r"(mbar), "r"(cnt) : "memory");
}
__device__ __forceinline__ void mbar_expect_tx(uint32_t mbar, uint32_t bytes) {
    asm volatile("mbarrier.arrive.expect_tx.shared.b64 _, [%0], %1;"
                 :: "r"(mbar), "r"(bytes) : "memory");
}
__device__ __forceinline__ void mbar_wait(uint32_t mbar, uint32_t phase) {
    asm volatile(
        "{\n\t.reg .pred P;\n\t"
        "W_%=:\n\t"
        "mbarrier.try_wait.parity.acquire.cta.shared::cta.b64 P, [%0], %1, 0x989680;\n\t"
        "@P bra D_%=;\n\t"
        "bra W_%=;\n\t"
        "D_%=:\n\t}"
        :: "r"(mbar), "r"(phase) : "memory");
}
__device__ __forceinline__ void bulk_copy(uint32_t dst_smem, const void* src,
                                          uint32_t bytes, uint32_t mbar) {
    asm volatile(
        "cp.async.bulk.shared::cluster.global.mbarrier::complete_tx::bytes "
        "[%0], [%1], %2, [%3];"
        :: "r"(dst_smem), "l"(src), "r"(bytes), "r"(mbar) : "memory");
}

// ---------------------------------------------------------------------------
// Kernel 1: split-K GEMM partials, bulk-copy (TMA-engine) weight stream.
// grid = (8 j-tiles, 16 k-chunks, 2 matrices) = 256 blocks, 256 threads.
// Pipeline: 8 stages of 8 k-rows, double-buffered 16KB smem stages; elected
// thread issues 2KB cp.async.bulk per row, mbarrier complete_tx per stage.
// Per thread: 2 cols x 16 batches (8 f32x2 pairs) = 16 f32x2 accumulators.
// Per k-step: 1 LDS.64 (weights) + 4 broadcast LDS.128 (acts) + 16 FFMA2.
// ---------------------------------------------------------------------------
__global__ __launch_bounds__(TPB) void gemm_part(
    const float* __restrict__ Wi, const float* __restrict__ Wh,
    const float* __restrict__ x,  const float* __restrict__ h)
{
    __shared__ float wsm[2][SK * JT];      // 2 x 16 KB weight stages
    __shared__ float sh_act[KC][Bb];       // 4 KB activations
    __shared__ unsigned long long mbar[2];

    const int jt  = blockIdx.x;            // 0..7
    const int kc  = blockIdx.y;            // 0..15
    const int mat = blockIdx.z;            // 0: Wi/x, 1: Wh/h
    const float* __restrict__ W   = mat ? Wh : Wi;
    const float* __restrict__ act = mat ? h  : x;
    const int k0  = kc * KC;
    const int tid = threadIdx.x;

    const uint32_t mb[2] = { smem_u32(&mbar[0]), smem_u32(&mbar[1]) };
    const uint32_t wdst[2] = { smem_u32(&wsm[0][0]), smem_u32(&wsm[1][0]) };
    const float* Wbase = W + (size_t)k0 * H4 + jt * JT;

    if (tid == 0) { mbar_init(mb[0], 1); mbar_init(mb[1], 1); }

    // stage activations: coalesced gmem read, smem scatter
    for (int i = tid; i < Bb * KC; i += TPB) {
        int b = i >> 6;
        int k = i & (KC - 1);
        sh_act[k][b] = act[b * 1024 + k0 + k];
    }
    __syncthreads();

    if (tid == 0) {
#pragma unroll
        for (int st = 0; st < 2; st++) {
            mbar_expect_tx(mb[st], STAGE_BYTES);
#pragma unroll
            for (int r = 0; r < SK; r++)
                bulk_copy(wdst[st] + r * ROW_BYTES,
                          Wbase + (size_t)(st * SK + r) * H4, ROW_BYTES, mb[st]);
        }
    }

    unsigned long long acc[2][8];          // [col][batch-pair]
#pragma unroll
    for (int c = 0; c < 2; c++)
#pragma unroll
        for (int q = 0; q < 8; q++) acc[c][q] = 0ull;

    for (int s = 0; s < NST; s++) {
        const int bi = s & 1;
        mbar_wait(mb[bi], (s >> 1) & 1);

#pragma unroll
        for (int r = 0; r < SK; r++) {
            const int k = s * SK + r;
            float2 w = *reinterpret_cast<const float2*>(&wsm[bi][r * JT + tid * 2]);
            ulonglong2 A0 = *reinterpret_cast<const ulonglong2*>(&sh_act[k][0]);
            ulonglong2 A1 = *reinterpret_cast<const ulonglong2*>(&sh_act[k][4]);
            ulonglong2 A2 = *reinterpret_cast<const ulonglong2*>(&sh_act[k][8]);
            ulonglong2 A3 = *reinterpret_cast<const ulonglong2*>(&sh_act[k][12]);
            unsigned long long w0 = pack2(w.x, w.x);
            unsigned long long w1 = pack2(w.y, w.y);
            acc[0][0] = fma2(w0, A0.x, acc[0][0]);
            acc[0][1] = fma2(w0, A0.y, acc[0][1]);
            acc[0][2] = fma2(w0, A1.x, acc[0][2]);
            acc[0][3] = fma2(w0, A1.y, acc[0][3]);
            acc[0][4] = fma2(w0, A2.x, acc[0][4]);
            acc[0][5] = fma2(w0, A2.y, acc[0][5]);
            acc[0][6] = fma2(w0, A3.x, acc[0][6]);
            acc[0][7] = fma2(w0, A3.y, acc[0][7]);
            acc[1][0] = fma2(w1, A0.x, acc[1][0]);
            acc[1][1] = fma2(w1, A0.y, acc[1][1]);
            acc[1][2] = fma2(w1, A1.x, acc[1][2]);
            acc[1][3] = fma2(w1, A1.y, acc[1][3]);
            acc[1][4] = fma2(w1, A2.x, acc[1][4]);
            acc[1][5] = fma2(w1, A2.y, acc[1][5]);
            acc[1][6] = fma2(w1, A3.x, acc[1][6]);
            acc[1][7] = fma2(w1, A3.y, acc[1][7]);
        }

        __syncthreads();                   // all threads done with buffer bi
        if (tid == 0 && s + 2 < NST) {
            mbar_expect_tx(mb[bi], STAGE_BYTES);
#pragma unroll
            for (int r = 0; r < SK; r++)
                bulk_copy(wdst[bi] + r * ROW_BYTES,
                          Wbase + (size_t)((s + 2) * SK + r) * H4, ROW_BYTES, mb[bi]);
        }
    }

    // epilogue: coalesced STG.128 into per-(split, q) float2 planes
    const int sp = mat * NKC + kc;
    const int j0 = jt * JT + tid * 2;
#pragma unroll
    for (int q = 0; q < 8; q++) {
        float2* plane = reinterpret_cast<float2*>(g_part) + (size_t)(sp * 8 + q) * H4;
        *reinterpret_cast<ulonglong2*>(plane + j0) =
            make_ulonglong2(acc[0][q], acc[1][q]);
    }
}

// ---------------------------------------------------------------------------
// Kernel 2: reduce 32 partials + biases -> g_ifgo.
// 16384 threads; thread = (batch-pair q, column-pair jp) -> 4 outputs.
// ---------------------------------------------------------------------------
__global__ __launch_bounds__(256) void reduce_bias(
    const float* __restrict__ Wib, const float* __restrict__ Whb)
{
    int t  = blockIdx.x * blockDim.x + threadIdx.x;  // 0..16383
    int jp = t & 2047;
    int q  = t >> 11;                                 // 0..7
    int j  = jp * 2;
    const float4* base = reinterpret_cast<const float4*>(g_part)
                       + (size_t)q * (H4 / 2) + jp;
    float4 v = make_float4(0.f, 0.f, 0.f, 0.f);
#pragma unroll
    for (int s = 0; s < NSPLIT; s++) {
        float4 p = base[(size_t)s * 4 * H4];          // 8 planes = 4*H4 float4
        v.x += p.x; v.y += p.y; v.z += p.z; v.w += p.w;
    }
    float2 bb = make_float2(Wib[j] + Whb[j], Wib[j + 1] + Whb[j + 1]);
    int be = q * 2;
    *reinterpret_cast<float2*>(g_ifgo + (size_t)be * H4 + j) =
        make_float2(v.x + bb.x, v.z + bb.y);
    *reinterpret_cast<float2*>(g_ifgo + (size_t)(be + 1) * H4 + j) =
        make_float2(v.y + bb.x, v.w + bb.y);
}

// ---------------------------------------------------------------------------
// Kernel 3: LSTM gates + state update.  out = [h_new (B*H) | c_new (B*H)]
// ---------------------------------------------------------------------------
__global__ __launch_bounds__(256) void gates_kernel(
    const float* __restrict__ c, float* __restrict__ out)
{
    int idx = blockIdx.x * blockDim.x + threadIdx.x;  // 0 .. B*H
    int b = idx >> 10;
    int n = idx & 1023;
    const float* row = g_ifgo + (size_t)b * H4;
    float iv = row[n];
    float fv = row[1024 + n];
    float gv = row[2048 + n];
    float ov = row[3072 + n];
    float ig = 1.0f / (1.0f + expf(-iv));
    float fg = 1.0f / (1.0f + expf(-fv));
    float gg = tanhf(gv);
    float og = 1.0f / (1.0f + expf(-ov));
    float cn = fg * c[idx] + ig * gg;
    float hn = og * tanhf(cn);
    out[idx] = hn;
    out[Bb * 1024 + idx] = cn;
}

// ---------------------------------------------------------------------------
// Inputs (metadata order): x, h, c, context, Wi, Wi_b, Wh, Wh_b, AZ_il, AZ_ir,
// AZ_hl, AZ_hr.  context / AZ_* are dead (multiplied by 0 in the reference).
// ---------------------------------------------------------------------------
extern "C" void kernel_launch(void* const* d_in, const int* in_sizes, int n_in,
                              void* d_out, int out_size)
{
    (void)in_sizes; (void)n_in; (void)out_size;
    const float* x   = (const float*)d_in[0];
    const float* h   = (const float*)d_in[1];
    const float* c   = (const float*)d_in[2];
    const float* Wi  = (const float*)d_in[4];
    const float* Wib = (const float*)d_in[5];
    const float* Wh  = (const float*)d_in[6];
    const float* Whb = (const float*)d_in[7];
    float* out = (float*)d_out;

    dim3 g1(8, NKC, 2);
    gemm_part<<<g1, TPB>>>(Wi, Wh, x, h);
    reduce_bias<<<16384 / 256, 256>>>(Wib, Whb);
    gates_kernel<<<(Bb * 1024) / 256, 256>>>(c, out);
}